// round 5
// baseline (speedup 1.0000x reference)
#include <cuda_runtime.h>
#include <cuda_bf16.h>

// out[i,j] = sigmoid( sum_h W2[h]*relu(A[i,h]+B[j,h]) + b2 )
//   A = Z@W1[:D] + b1, B = Z@W1[D:].
// Identity: relu(a+b) = max(a,-b)+b  =>  logits = sum_h w*max(a,-b) + C_j + b2.
#define NN 2048
#define DD 32
#define HH 64

__device__ float g_A [NN * HH];  // A[n][h]
__device__ float g_nB[NN * HH];  // -B[n][h]
__device__ float g_C [NN];       // C[j] = sum_h W2[h]*B[j,h]

// ---------------------------------------------------------------------------
// Prep: A, -B, C. 512 blocks x 256 threads. ~1.5us.
// ---------------------------------------------------------------------------
__global__ void prep_kernel(const float* __restrict__ Z,
                            const float* __restrict__ W1,
                            const float* __restrict__ b1,
                            const float* __restrict__ W2) {
    __shared__ float zs[4][DD];
    __shared__ float cbuf[4][HH];
    int tid = threadIdx.x;
    int nblk = blockIdx.x * 4;
    if (tid < 4 * DD) {
        zs[tid >> 5][tid & 31] = Z[(nblk + (tid >> 5)) * DD + (tid & 31)];
    }
    __syncthreads();
    int local_n = tid >> 6;
    int h = tid & 63;
    int n = nblk + local_n;
    float sa = b1[h];
    float sb = 0.0f;
#pragma unroll
    for (int d = 0; d < DD; d++) {
        float z = zs[local_n][d];
        sa = fmaf(z, W1[d * HH + h], sa);
        sb = fmaf(z, W1[(DD + d) * HH + h], sb);
    }
    g_A [n * HH + h] = sa;
    g_nB[n * HH + h] = -sb;
    cbuf[local_n][h] = sb * W2[h];
    __syncthreads();
    if (tid < 4) {
        float c = 0.0f;
#pragma unroll
        for (int k = 0; k < HH; k++) c += cbuf[tid][k];
        g_C[nblk + tid] = c;
    }
}

// ---------------------------------------------------------------------------
// Persistent pair kernel: grid = 592 CTAs (4/SM x 148), each CTA processes
// tiles {bid, bid+592} of the 32x32 grid of 64x64 tiles. Every SM gets
// exactly 7 tile-works regardless of the bid->SM permutation (one bid per
// 148-chunk per SM) -> perfectly balanced single wave.
// Per-thread 4x4 pairs, interleaved lanes (i=ty+16*ii, j=tx+16*jj):
// conflict-free LDS.64 with SROW=66.
// Inner math is pure scalar C++: 2 FMNMX + 2 FFMA per pair per 2h. No
// inline-asm register-boundary MOVs.
// ---------------------------------------------------------------------------
#define SROW 66
#define NTILES 1024   // 32 x 32
#define GRID 592

__device__ __forceinline__ float sigmoid_fast(float x) {
    float t;
    asm("tanh.approx.f32 %0, %1;" : "=f"(t) : "f"(0.5f * x));
    return fmaf(0.5f, t, 0.5f);
}

__global__ __launch_bounds__(256, 4)
void pair_kernel(const float* __restrict__ W2,
                 const float* __restrict__ b2,
                 float* __restrict__ out) {
    __shared__ float As[64 * SROW];
    __shared__ float Bs[64 * SROW];   // holds -B
    __shared__ float ws[HH];
    __shared__ float Cs[64];

    int tid = threadIdx.x;
    int tx = tid & 15;   // j lane
    int ty = tid >> 4;   // i lane
    float bias = b2[0];

    for (int t = blockIdx.x; t < NTILES; t += GRID) {
        int bj = (t & 31) * 64;
        int bi = (t >> 5) * 64;

        __syncthreads();   // previous iteration's smem reads done
        for (int idx = tid; idx < 64 * HH; idx += 256) {
            int r = idx >> 6;
            int h = idx & 63;
            As[r * SROW + h] = g_A [(bi + r) * HH + h];
            Bs[r * SROW + h] = g_nB[(bj + r) * HH + h];
        }
        if (tid < HH) ws[tid] = W2[tid];
        if (tid >= 128 && tid < 192) Cs[tid - 128] = g_C[bj + (tid - 128)];
        __syncthreads();

        float acc0[4][4], acc1[4][4];
#pragma unroll
        for (int ii = 0; ii < 4; ii++)
#pragma unroll
            for (int jj = 0; jj < 4; jj++) { acc0[ii][jj] = 0.0f; acc1[ii][jj] = 0.0f; }

        const float* arow0 = &As[ty * SROW];
        const float* brow0 = &Bs[tx * SROW];

#pragma unroll 4
        for (int h = 0; h < HH; h += 2) {
            float2 wv = *(const float2*)&ws[h];
            float2 a2[4], b2v[4];
#pragma unroll
            for (int ii = 0; ii < 4; ii++)
                a2[ii] = *(const float2*)&arow0[ii * 16 * SROW + h];
#pragma unroll
            for (int jj = 0; jj < 4; jj++)
                b2v[jj] = *(const float2*)&brow0[jj * 16 * SROW + h];
#pragma unroll
            for (int jj = 0; jj < 4; jj++) {
#pragma unroll
                for (int ii = 0; ii < 4; ii++) {
                    float t0 = fmaxf(a2[ii].x, b2v[jj].x);
                    float t1 = fmaxf(a2[ii].y, b2v[jj].y);
                    acc0[ii][jj] = fmaf(t0, wv.x, acc0[ii][jj]);
                    acc1[ii][jj] = fmaf(t1, wv.y, acc1[ii][jj]);
                }
            }
        }

#pragma unroll
        for (int ii = 0; ii < 4; ii++) {
            int gi = bi + ty + ii * 16;
#pragma unroll
            for (int jj = 0; jj < 4; jj++) {
                int gj = bj + tx + jj * 16;
                float x = acc0[ii][jj] + acc1[ii][jj] + Cs[tx + jj * 16] + bias;
                out[gi * NN + gj] = sigmoid_fast(x);   // coalesced across tx
            }
        }
    }
}

extern "C" void kernel_launch(void* const* d_in, const int* in_sizes, int n_in,
                              void* d_out, int out_size) {
    const float* Z  = (const float*)d_in[0];
    const float* W1 = (const float*)d_in[1];
    const float* b1 = (const float*)d_in[2];
    const float* W2 = (const float*)d_in[3];
    const float* b2 = (const float*)d_in[4];
    float* out = (float*)d_out;

    prep_kernel<<<NN / 4, 256>>>(Z, W1, b1, W2);
    pair_kernel<<<GRID, 256>>>(W2, b2, out);
}

// round 6
// speedup vs baseline: 1.0591x; 1.0591x over previous
#include <cuda_runtime.h>
#include <cuda_bf16.h>

// out[i,j] = sigmoid( sum_h W2[h]*relu(A[i,h]+B[j,h]) + b2 )
//   A = Z@W1[:D] + b1, B = Z@W1[D:].
// Identity: relu(a+b) = max(a,-b)+b  =>  logits = sum_h w*max(a,-b) + C_j + b2.
#define NN 2048
#define DD 32
#define HH 64

__device__ float g_A [NN * HH];  // A[n][h]
__device__ float g_nB[NN * HH];  // -B[n][h]
__device__ float g_C [NN];       // C[j] = sum_h W2[h]*B[j,h]

typedef unsigned long long u64t;

// Fused: acc(f32x2) += max2(a, b) * w.  Single asm block so the b64 pack is a
// virtual register ptxas can allocate as the FMNMX dest pair (no real MOVs).
// Per 2 pair-h: 2x FMNMX (alu) + 1x FFMA2 (fma) = 3 issue slots.
__device__ __forceinline__ void max_fma2(u64t& acc, float ax, float ay,
                                         float bx, float by, u64t w) {
    asm("{\n\t"
        ".reg .f32 lo, hi;\n\t"
        ".reg .b64 t;\n\t"
        "max.f32 lo, %1, %3;\n\t"
        "max.f32 hi, %2, %4;\n\t"
        "mov.b64 t, {lo, hi};\n\t"
        "fma.rn.f32x2 %0, t, %5, %0;\n\t"
        "}" : "+l"(acc) : "f"(ax), "f"(ay), "f"(bx), "f"(by), "l"(w));
}

// ---------------------------------------------------------------------------
// Prep: A, -B, C. 512 blocks x 256 threads. ~1.5us.
// ---------------------------------------------------------------------------
__global__ void prep_kernel(const float* __restrict__ Z,
                            const float* __restrict__ W1,
                            const float* __restrict__ b1,
                            const float* __restrict__ W2) {
    __shared__ float zs[4][DD];
    __shared__ float cbuf[4][HH];
    int tid = threadIdx.x;
    int nblk = blockIdx.x * 4;
    if (tid < 4 * DD) {
        zs[tid >> 5][tid & 31] = Z[(nblk + (tid >> 5)) * DD + (tid & 31)];
    }
    __syncthreads();
    int local_n = tid >> 6;
    int h = tid & 63;
    int n = nblk + local_n;
    float sa = b1[h];
    float sb = 0.0f;
#pragma unroll
    for (int d = 0; d < DD; d++) {
        float z = zs[local_n][d];
        sa = fmaf(z, W1[d * HH + h], sa);
        sb = fmaf(z, W1[(DD + d) * HH + h], sb);
    }
    g_A [n * HH + h] = sa;
    g_nB[n * HH + h] = -sb;
    cbuf[local_n][h] = sb * W2[h];
    __syncthreads();
    if (tid < 4) {
        float c = 0.0f;
#pragma unroll
        for (int k = 0; k < HH; k++) c += cbuf[tid][k];
        g_C[nblk + tid] = c;
    }
}

// ---------------------------------------------------------------------------
// Persistent pair kernel: grid = 592 (4 CTAs/SM x 148), CTA b does tiles
// {b, b+592}. 64x64 tile, 256 threads, 4x4 pairs/thread, interleaved lanes
// (i=ty+16*ii, j=tx+16*jj): conflict-free LDS.64 at SROW=66.
// Inner: 9 LDS.64 + 16 x (2 FMNMX + FFMA2) = 57 slots per 2h-step.
// ---------------------------------------------------------------------------
#define SROW 66
#define NTILES 1024   // 32 x 32
#define GRID 592

__device__ __forceinline__ float sigmoid_fast(float x) {
    float t;
    asm("tanh.approx.f32 %0, %1;" : "=f"(t) : "f"(0.5f * x));
    return fmaf(0.5f, t, 0.5f);
}

__global__ __launch_bounds__(256, 4)
void pair_kernel(const float* __restrict__ W2,
                 const float* __restrict__ b2,
                 float* __restrict__ out) {
    __shared__ float As[64 * SROW];
    __shared__ float Bs[64 * SROW];   // holds -B
    __shared__ float ws[HH];
    __shared__ float Cs[64];

    int tid = threadIdx.x;
    int tx = tid & 15;   // j lane
    int ty = tid >> 4;   // i lane
    float bias = b2[0];

    // W2 is tile-invariant: stage once (first in-loop barrier orders it).
    if (tid < HH) ws[tid] = W2[tid];

    for (int t = blockIdx.x; t < NTILES; t += GRID) {
        int bj = (t & 31) * 64;
        int bi = (t >> 5) * 64;

        __syncthreads();   // prev iteration's reads done / ws visible
        for (int idx = tid; idx < 64 * HH; idx += 256) {
            int r = idx >> 6;
            int h = idx & 63;
            As[r * SROW + h] = g_A [(bi + r) * HH + h];
            Bs[r * SROW + h] = g_nB[(bj + r) * HH + h];
        }
        if (tid >= 128 && tid < 192) Cs[tid - 128] = g_C[bj + (tid - 128)];
        __syncthreads();

        u64t acc[4][4];
#pragma unroll
        for (int ii = 0; ii < 4; ii++)
#pragma unroll
            for (int jj = 0; jj < 4; jj++) acc[ii][jj] = 0ull;

        const float* arow0 = &As[ty * SROW];
        const float* brow0 = &Bs[tx * SROW];

#pragma unroll 4
        for (int h = 0; h < HH; h += 2) {
            u64t w2h = *(const u64t*)&ws[h];
            float2 a2[4], bv[4];
#pragma unroll
            for (int ii = 0; ii < 4; ii++)
                a2[ii] = *(const float2*)&arow0[ii * 16 * SROW + h];
#pragma unroll
            for (int jj = 0; jj < 4; jj++)
                bv[jj] = *(const float2*)&brow0[jj * 16 * SROW + h];
#pragma unroll
            for (int jj = 0; jj < 4; jj++) {
#pragma unroll
                for (int ii = 0; ii < 4; ii++) {
                    max_fma2(acc[ii][jj], a2[ii].x, a2[ii].y,
                             bv[jj].x, bv[jj].y, w2h);
                }
            }
        }

#pragma unroll
        for (int ii = 0; ii < 4; ii++) {
            int gi = bi + ty + ii * 16;
#pragma unroll
            for (int jj = 0; jj < 4; jj++) {
                int gj = bj + tx + jj * 16;
                float2 v = *(float2*)&acc[ii][jj];
                float x = v.x + v.y + Cs[tx + jj * 16] + bias;
                out[gi * NN + gj] = sigmoid_fast(x);   // coalesced across tx
            }
        }
    }
}

extern "C" void kernel_launch(void* const* d_in, const int* in_sizes, int n_in,
                              void* d_out, int out_size) {
    const float* Z  = (const float*)d_in[0];
    const float* W1 = (const float*)d_in[1];
    const float* b1 = (const float*)d_in[2];
    const float* W2 = (const float*)d_in[3];
    const float* b2 = (const float*)d_in[4];
    float* out = (float*)d_out;

    prep_kernel<<<NN / 4, 256>>>(Z, W1, b1, W2);
    pair_kernel<<<GRID, 256>>>(W2, b2, out);
}

// round 7
// speedup vs baseline: 1.0734x; 1.0136x over previous
#include <cuda_runtime.h>
#include <cuda_bf16.h>

// out[i,j] = sigmoid( sum_h W2[h]*relu(A[i,h]+B[j,h]) + b2 )
//   A = Z@W1[:D] + b1, B = Z@W1[D:].
// Identity: relu(a+b) = max(a,-b)+b  =>  logits = sum_h w*max(a,-b) + C_j + b2.
#define NN 2048
#define DD 32
#define HH 64

__device__ float g_A [NN * HH];  // A[n][h]
__device__ float g_nB[NN * HH];  // -B[n][h]
__device__ float g_C [NN];       // C[j] = sum_h W2[h]*B[j,h]
__device__ int   g_ctr;          // work-stealing tile counter

typedef unsigned long long u64t;

// Fused: acc(f32x2) += max2(a, b) * w.  Single asm block: the b64 pack is a
// virtual register ptxas allocates as the FMNMX dest pair (no real MOVs).
// Per 2 pair-h: 2x FMNMX (alu) + 1x FFMA2 (fma) = 3 issue slots.
__device__ __forceinline__ void max_fma2(u64t& acc, float ax, float ay,
                                         float bx, float by, u64t w) {
    asm("{\n\t"
        ".reg .f32 lo, hi;\n\t"
        ".reg .b64 t;\n\t"
        "max.f32 lo, %1, %3;\n\t"
        "max.f32 hi, %2, %4;\n\t"
        "mov.b64 t, {lo, hi};\n\t"
        "fma.rn.f32x2 %0, t, %5, %0;\n\t"
        "}" : "+l"(acc) : "f"(ax), "f"(ay), "f"(bx), "f"(by), "l"(w));
}

// ---------------------------------------------------------------------------
// Prep: A, -B, C, and reset the work counter. 512 blocks x 256 threads.
// ---------------------------------------------------------------------------
#define GRID 592
__global__ void prep_kernel(const float* __restrict__ Z,
                            const float* __restrict__ W1,
                            const float* __restrict__ b1,
                            const float* __restrict__ W2) {
    __shared__ float zs[4][DD];
    __shared__ float cbuf[4][HH];
    int tid = threadIdx.x;
    int nblk = blockIdx.x * 4;
    if (blockIdx.x == 0 && tid == 0) g_ctr = GRID;   // reset stealing queue
    if (tid < 4 * DD) {
        zs[tid >> 5][tid & 31] = Z[(nblk + (tid >> 5)) * DD + (tid & 31)];
    }
    __syncthreads();
    int local_n = tid >> 6;
    int h = tid & 63;
    int n = nblk + local_n;
    float sa = b1[h];
    float sb = 0.0f;
#pragma unroll
    for (int d = 0; d < DD; d++) {
        float z = zs[local_n][d];
        sa = fmaf(z, W1[d * HH + h], sa);
        sb = fmaf(z, W1[(DD + d) * HH + h], sb);
    }
    g_A [n * HH + h] = sa;
    g_nB[n * HH + h] = -sb;
    cbuf[local_n][h] = sb * W2[h];
    __syncthreads();
    if (tid < 4) {
        float c = 0.0f;
#pragma unroll
        for (int k = 0; k < HH; k++) c += cbuf[tid][k];
        g_C[nblk + tid] = c;
    }
}

// ---------------------------------------------------------------------------
// Persistent pair kernel with atomic work-stealing: 592 CTAs (4/SM) pop
// 64x64 tiles from a global queue -> no idle second half, tail = 1 tile.
// Per-thread 4x4 pairs, interleaved lanes (i=ty+16*ii, j=tx+16*jj):
// conflict-free LDS.64 at SROW=66.
// ---------------------------------------------------------------------------
#define SROW 66
#define NTILES 1024   // 32 x 32

__device__ __forceinline__ float sigmoid_fast(float x) {
    float t;
    asm("tanh.approx.f32 %0, %1;" : "=f"(t) : "f"(0.5f * x));
    return fmaf(0.5f, t, 0.5f);
}

__global__ __launch_bounds__(256, 4)
void pair_kernel(const float* __restrict__ W2,
                 const float* __restrict__ b2,
                 float* __restrict__ out) {
    __shared__ float As[64 * SROW];
    __shared__ float Bs[64 * SROW];   // holds -B
    __shared__ float ws[HH];
    __shared__ int   next_t;

    int tid = threadIdx.x;
    int tx = tid & 15;   // j lane
    int ty = tid >> 4;   // i lane
    float bias = b2[0];

    if (tid < HH) ws[tid] = W2[tid];   // tile-invariant; ordered by 1st barrier

    int t = blockIdx.x;
    while (t < NTILES) {
        int bj = (t & 31) * 64;
        int bi = (t >> 5) * 64;

        __syncthreads();   // prev reads done / ws visible
        for (int idx = tid; idx < 64 * HH; idx += 256) {
            int r = idx >> 6;
            int h = idx & 63;
            As[r * SROW + h] = g_A [(bi + r) * HH + h];
            Bs[r * SROW + h] = g_nB[(bj + r) * HH + h];
        }
        if (tid == 0) next_t = atomicAdd(&g_ctr, 1);   // overlap pop w/ staging
        __syncthreads();

        u64t acc[4][4];
#pragma unroll
        for (int ii = 0; ii < 4; ii++)
#pragma unroll
            for (int jj = 0; jj < 4; jj++) acc[ii][jj] = 0ull;

        const float* arow0 = &As[ty * SROW];
        const float* brow0 = &Bs[tx * SROW];

#pragma unroll 4
        for (int h = 0; h < HH; h += 2) {
            u64t w2h = *(const u64t*)&ws[h];
            float2 a2[4], bv[4];
#pragma unroll
            for (int ii = 0; ii < 4; ii++)
                a2[ii] = *(const float2*)&arow0[ii * 16 * SROW + h];
#pragma unroll
            for (int jj = 0; jj < 4; jj++)
                bv[jj] = *(const float2*)&brow0[jj * 16 * SROW + h];
#pragma unroll
            for (int jj = 0; jj < 4; jj++) {
#pragma unroll
                for (int ii = 0; ii < 4; ii++) {
                    max_fma2(acc[ii][jj], a2[ii].x, a2[ii].y,
                             bv[jj].x, bv[jj].y, w2h);
                }
            }
        }

#pragma unroll
        for (int ii = 0; ii < 4; ii++) {
            int gi = bi + ty + ii * 16;
#pragma unroll
            for (int jj = 0; jj < 4; jj++) {
                int gj = bj + tx + jj * 16;
                float2 v = *(float2*)&acc[ii][jj];
                float x = v.x + v.y + __ldg(&g_C[gj]) + bias;
                out[gi * NN + gj] = sigmoid_fast(x);   // coalesced across tx
            }
        }

        t = next_t;   // all threads read the popped tile (barrier at loop top
                      // is AFTER this read? no: next_t read here, written under
                      // barrier protection above; reads happen before next
                      // iteration's top barrier rewrites it) 
    }
}

extern "C" void kernel_launch(void* const* d_in, const int* in_sizes, int n_in,
                              void* d_out, int out_size) {
    const float* Z  = (const float*)d_in[0];
    const float* W1 = (const float*)d_in[1];
    const float* b1 = (const float*)d_in[2];
    const float* W2 = (const float*)d_in[3];
    const float* b2 = (const float*)d_in[4];
    float* out = (float*)d_out;

    prep_kernel<<<NN / 4, 256>>>(Z, W1, b1, W2);
    pair_kernel<<<GRID, 256>>>(W2, b2, out);
}

// round 8
// speedup vs baseline: 1.2339x; 1.1495x over previous
#include <cuda_runtime.h>
#include <cuda_bf16.h>

// out[i,j] = sigmoid( sum_h W2[h]*relu(A[i,h]+B[j,h]) + b2 )
//   A = Z@W1[:D] + b1, B = Z@W1[D:].
// Identity: relu(a+b) = max(a,-b)+b  =>  logits = sum_h w*max(a,-b) + C_j + b2.
#define NN 2048
#define DD 32
#define HH 64

__device__ float g_A [NN * HH];  // A[n][h]
__device__ float g_nB[NN * HH];  // -B[n][h]
__device__ float g_C [NN];       // C[j] = sum_h W2[h]*B[j,h]
__device__ int   g_ctr;          // work-stealing tile counter

typedef unsigned long long u64t;

// Fused: acc(f32x2) += max2(a, b) * w.  2x FMNMX (alu) + 1x FFMA2 (fma).
__device__ __forceinline__ void max_fma2(u64t& acc, float ax, float ay,
                                         float bx, float by, u64t w) {
    asm("{\n\t"
        ".reg .f32 lo, hi;\n\t"
        ".reg .b64 t;\n\t"
        "max.f32 lo, %1, %3;\n\t"
        "max.f32 hi, %2, %4;\n\t"
        "mov.b64 t, {lo, hi};\n\t"
        "fma.rn.f32x2 %0, t, %5, %0;\n\t"
        "}" : "+l"(acc) : "f"(ax), "f"(ay), "f"(bx), "f"(by), "l"(w));
}

#define GRID 444   // 3 CTAs/SM x 148 SMs

// ---------------------------------------------------------------------------
// Prep: A, -B, C, reset work counter. 512 blocks x 256 threads.
// ---------------------------------------------------------------------------
__global__ void prep_kernel(const float* __restrict__ Z,
                            const float* __restrict__ W1,
                            const float* __restrict__ b1,
                            const float* __restrict__ W2) {
    __shared__ float zs[4][DD];
    __shared__ float cbuf[4][HH];
    int tid = threadIdx.x;
    int nblk = blockIdx.x * 4;
    if (blockIdx.x == 0 && tid == 0) g_ctr = GRID;
    if (tid < 4 * DD) {
        zs[tid >> 5][tid & 31] = Z[(nblk + (tid >> 5)) * DD + (tid & 31)];
    }
    __syncthreads();
    int local_n = tid >> 6;
    int h = tid & 63;
    int n = nblk + local_n;
    float sa = b1[h];
    float sb = 0.0f;
#pragma unroll
    for (int d = 0; d < DD; d++) {
        float z = zs[local_n][d];
        sa = fmaf(z, W1[d * HH + h], sa);
        sb = fmaf(z, W1[(DD + d) * HH + h], sb);
    }
    g_A [n * HH + h] = sa;
    g_nB[n * HH + h] = -sb;
    cbuf[local_n][h] = sb * W2[h];
    __syncthreads();
    if (tid < 4) {
        float c = 0.0f;
#pragma unroll
        for (int k = 0; k < HH; k++) c += cbuf[tid][k];
        g_C[nblk + tid] = c;
    }
}

// ---------------------------------------------------------------------------
// Persistent pair kernel, 3 CTAs/SM, atomic work-stealing, SOFTWARE-PIPELINED
// inner loop: ping-pong operand buffers X/Y so each step's LDS results are
// consumed one full step (48 math slots) after issue -> LDS latency hidden
// within each warp, independent of other warps' state.
// 64x64 tile, 4x4 pairs/thread, interleaved lanes, conflict-free LDS.64.
// ---------------------------------------------------------------------------
#define SROW 66
#define NTILES 1024

__device__ __forceinline__ float sigmoid_fast(float x) {
    float t;
    asm("tanh.approx.f32 %0, %1;" : "=f"(t) : "f"(0.5f * x));
    return fmaf(0.5f, t, 0.5f);
}

__global__ __launch_bounds__(256, 3)
void pair_kernel(const float* __restrict__ W2,
                 const float* __restrict__ b2,
                 float* __restrict__ out) {
    __shared__ float As[64 * SROW];
    __shared__ float Bs[64 * SROW];   // holds -B
    __shared__ float ws[68];          // 64 used + 4 pad for wrapped prologue load
    __shared__ int   next_t;

    int tid = threadIdx.x;
    int tx = tid & 15;   // j lane
    int ty = tid >> 4;   // i lane
    float bias = b2[0];

    if (tid < HH) ws[tid] = W2[tid];
    if (tid >= 64 && tid < 68) ws[tid] = 0.0f;   // pad (never used in math)

    int t = blockIdx.x;
    while (t < NTILES) {
        int bj = (t & 31) * 64;
        int bi = (t >> 5) * 64;

        __syncthreads();
        for (int idx = tid; idx < 64 * HH; idx += 256) {
            int r = idx >> 6;
            int h = idx & 63;
            As[r * SROW + h] = g_A [(bi + r) * HH + h];
            Bs[r * SROW + h] = g_nB[(bj + r) * HH + h];
        }
        if (tid == 0) next_t = atomicAdd(&g_ctr, 1);
        __syncthreads();

        u64t acc[4][4];
#pragma unroll
        for (int ii = 0; ii < 4; ii++)
#pragma unroll
            for (int jj = 0; jj < 4; jj++) acc[ii][jj] = 0ull;

        const float* arow0 = &As[ty * SROW];
        const float* brow0 = &Bs[tx * SROW];

        // Pipeline buffers
        float2 ax[4], bx[4];  u64t wx;   // buffer X
        float2 ay[4], by[4];  u64t wy;   // buffer Y

        // Prologue: load h=0 into X
        wx = *(const u64t*)&ws[0];
#pragma unroll
        for (int ii = 0; ii < 4; ii++) ax[ii] = *(const float2*)&arow0[ii * 16 * SROW];
#pragma unroll
        for (int jj = 0; jj < 4; jj++) bx[jj] = *(const float2*)&brow0[jj * 16 * SROW];

#pragma unroll 2
        for (int hb = 0; hb < HH; hb += 4) {
            // load Y <- hb+2 (always valid: hb+2 <= 62)
            wy = *(const u64t*)&ws[hb + 2];
#pragma unroll
            for (int ii = 0; ii < 4; ii++)
                ay[ii] = *(const float2*)&arow0[ii * 16 * SROW + hb + 2];
#pragma unroll
            for (int jj = 0; jj < 4; jj++)
                by[jj] = *(const float2*)&brow0[jj * 16 * SROW + hb + 2];
            // compute X (hb)
#pragma unroll
            for (int jj = 0; jj < 4; jj++)
#pragma unroll
                for (int ii = 0; ii < 4; ii++)
                    max_fma2(acc[ii][jj], ax[ii].x, ax[ii].y, bx[jj].x, bx[jj].y, wx);
            // load X <- hb+4 (at hb=60 this reads h=64..65: padded, unused)
            wx = *(const u64t*)&ws[hb + 4];
#pragma unroll
            for (int ii = 0; ii < 4; ii++)
                ax[ii] = *(const float2*)&arow0[ii * 16 * SROW + hb + 4];
#pragma unroll
            for (int jj = 0; jj < 4; jj++)
                bx[jj] = *(const float2*)&brow0[jj * 16 * SROW + hb + 4];
            // compute Y (hb+2)
#pragma unroll
            for (int jj = 0; jj < 4; jj++)
#pragma unroll
                for (int ii = 0; ii < 4; ii++)
                    max_fma2(acc[ii][jj], ay[ii].x, ay[ii].y, by[jj].x, by[jj].y, wy);
        }

#pragma unroll
        for (int ii = 0; ii < 4; ii++) {
            int gi = bi + ty + ii * 16;
#pragma unroll
            for (int jj = 0; jj < 4; jj++) {
                int gj = bj + tx + jj * 16;
                float2 v = *(float2*)&acc[ii][jj];
                float x = v.x + v.y + __ldg(&g_C[gj]) + bias;
                out[gi * NN + gj] = sigmoid_fast(x);   // coalesced across tx
            }
        }

        t = next_t;
    }
}

extern "C" void kernel_launch(void* const* d_in, const int* in_sizes, int n_in,
                              void* d_out, int out_size) {
    const float* Z  = (const float*)d_in[0];
    const float* W1 = (const float*)d_in[1];
    const float* b1 = (const float*)d_in[2];
    const float* W2 = (const float*)d_in[3];
    const float* b2 = (const float*)d_in[4];
    float* out = (float*)d_out;

    prep_kernel<<<NN / 4, 256>>>(Z, W1, b1, W2);
    pair_kernel<<<GRID, 256>>>(W2, b2, out);
}

// round 11
// speedup vs baseline: 1.3084x; 1.0603x over previous
#include <cuda_runtime.h>
#include <cuda_bf16.h>
#include <cstdint>

// out[i,j] = sigmoid( sum_h W2[h]*relu(A[i,h]+B[j,h]) + b2 )
//   A = Z@W1[:D] + b1, B = Z@W1[D:].
// Identity: relu(a+b) = max(a,-b)+b  =>  logits = sum_h w*max(a,-b) + C_j + b2.
#define NN 2048
#define DD 32
#define HH 64

__device__ float g_A [NN * HH];  // A[n][h]
__device__ float g_nB[NN * HH];  // -B[n][h]
__device__ float g_C [NN];       // C[j] = sum_h W2[h]*B[j,h]
__device__ int   g_ctr;          // work-stealing tile counter

typedef unsigned long long u64t;

// Fused: acc(f32x2) += max2(a, b) * w.  2x FMNMX (alu) + 1x FFMA2 (fma).
__device__ __forceinline__ void max_fma2(u64t& acc, float ax, float ay,
                                         float bx, float by, u64t w) {
    asm("{\n\t"
        ".reg .f32 lo, hi;\n\t"
        ".reg .b64 t;\n\t"
        "max.f32 lo, %1, %3;\n\t"
        "max.f32 hi, %2, %4;\n\t"
        "mov.b64 t, {lo, hi};\n\t"
        "fma.rn.f32x2 %0, t, %5, %0;\n\t"
        "}" : "+l"(acc) : "f"(ax), "f"(ay), "f"(bx), "f"(by), "l"(w));
}

__device__ __forceinline__ void cp8(float* s, const float* g) {
    unsigned int sa = (unsigned int)__cvta_generic_to_shared(s);
    asm volatile("cp.async.ca.shared.global [%0], [%1], 8;" :: "r"(sa), "l"(g));
}

#define GRID 444   // 3 CTAs/SM x 148 SMs

// ---------------------------------------------------------------------------
// Prep: A, -B, C, reset work counter. 512 blocks x 256 threads.
// ---------------------------------------------------------------------------
__global__ void prep_kernel(const float* __restrict__ Z,
                            const float* __restrict__ W1,
                            const float* __restrict__ b1,
                            const float* __restrict__ W2) {
    __shared__ float zs[4][DD];
    __shared__ float cbuf[4][HH];
    int tid = threadIdx.x;
    int nblk = blockIdx.x * 4;
    if (blockIdx.x == 0 && tid == 0) g_ctr = GRID;
    if (tid < 4 * DD) {
        zs[tid >> 5][tid & 31] = Z[(nblk + (tid >> 5)) * DD + (tid & 31)];
    }
    __syncthreads();
    int local_n = tid >> 6;
    int h = tid & 63;
    int n = nblk + local_n;
    float sa = b1[h];
    float sb = 0.0f;
#pragma unroll
    for (int d = 0; d < DD; d++) {
        float z = zs[local_n][d];
        sa = fmaf(z, W1[d * HH + h], sa);
        sb = fmaf(z, W1[(DD + d) * HH + h], sb);
    }
    g_A [n * HH + h] = sa;
    g_nB[n * HH + h] = -sb;
    cbuf[local_n][h] = sb * W2[h];
    __syncthreads();
    if (tid < 4) {
        float c = 0.0f;
#pragma unroll
        for (int k = 0; k < HH; k++) c += cbuf[tid][k];
        g_C[nblk + tid] = c;
    }
}

// ---------------------------------------------------------------------------
// Persistent pair kernel, 3 CTAs/SM, work-stealing, register-pipelined math,
// and cp.async DOUBLE-BUFFERED smem staging: next tile streams in while the
// current one is computed -> no exposed LDG latency, barriers are cheap.
// 64x64 tile, 4x4 pairs/thread, interleaved lanes, conflict-free LDS.64
// (SROW=66; 264B row stride is 8B-aligned for cp.async size-8).
// ---------------------------------------------------------------------------
#define SROW 66
#define ABUF (64 * SROW)
#define NTILES 1024

__device__ __forceinline__ float sigmoid_fast(float x) {
    float t;
    asm("tanh.approx.f32 %0, %1;" : "=f"(t) : "f"(0.5f * x));
    return fmaf(0.5f, t, 0.5f);
}

__global__ __launch_bounds__(256, 3)
void pair_kernel(const float* __restrict__ W2,
                 const float* __restrict__ b2,
                 float* __restrict__ out) {
    extern __shared__ float smem[];
    // layout: As[2] | Bs[2] | ws(68) | next_t
    float* ws = smem + 4 * ABUF;
    int* next_s = (int*)(ws + 68);

    int tid = threadIdx.x;
    int tx = tid & 15;   // j lane
    int ty = tid >> 4;   // i lane
    float bias = b2[0];

    if (tid < HH) ws[tid] = W2[tid];
    if (tid >= 64 && tid < 68) ws[tid] = 0.0f;   // pad for wrapped prefetch

    // staging geometry: 8B chunks; thread covers rows r0+8c, chunk h2
    int r0 = tid >> 5;            // 0..7
    int h2 = (tid & 31) * 2;      // word offset of 8B chunk

    int t = blockIdx.x;
    int p = 0;
    // Prologue: stage tile t into buffer 0
    {
        int bj = (t & 31) * 64, bi = (t >> 5) * 64;
        const float* gA = g_A  + (bi + r0) * HH + h2;
        const float* gB = g_nB + (bj + r0) * HH + h2;
        float* sA = smem + r0 * SROW + h2;             // As[0]
        float* sB = smem + 2 * ABUF + r0 * SROW + h2;  // Bs[0]
#pragma unroll
        for (int c = 0; c < 8; c++) {
            cp8(sA + c * 8 * SROW, gA + c * 8 * HH);
            cp8(sB + c * 8 * SROW, gB + c * 8 * HH);
        }
        asm volatile("cp.async.commit_group;");
    }

    while (true) {
        if (tid == 0) *next_s = atomicAdd(&g_ctr, 1);
        __syncthreads();                 // prev compute on buf p^1 done; next_s visible
        int tn = *next_s;
        if (tn < NTILES) {               // stage next tile into buf p^1
            int bj = (tn & 31) * 64, bi = (tn >> 5) * 64;
            const float* gA = g_A  + (bi + r0) * HH + h2;
            const float* gB = g_nB + (bj + r0) * HH + h2;
            float* sA = smem + (p ^ 1) * ABUF + r0 * SROW + h2;
            float* sB = smem + (2 + (p ^ 1)) * ABUF + r0 * SROW + h2;
#pragma unroll
            for (int c = 0; c < 8; c++) {
                cp8(sA + c * 8 * SROW, gA + c * 8 * HH);
                cp8(sB + c * 8 * SROW, gB + c * 8 * HH);
            }
        }
        asm volatile("cp.async.commit_group;");   // group even if empty
        asm volatile("cp.async.wait_group 1;");   // buf p data arrived
        __syncthreads();                          // visible to all warps

        int bj = (t & 31) * 64, bi = (t >> 5) * 64;
        const float* arow0 = smem + p * ABUF + ty * SROW;
        const float* brow0 = smem + (2 + p) * ABUF + tx * SROW;

        u64t acc[4][4];
#pragma unroll
        for (int ii = 0; ii < 4; ii++)
#pragma unroll
            for (int jj = 0; jj < 4; jj++) acc[ii][jj] = 0ull;

        // Register-pipelined math: ping-pong X/Y operand buffers.
        float2 ax[4], bx[4];  u64t wx;
        float2 ay[4], by[4];  u64t wy;
        wx = *(const u64t*)&ws[0];
#pragma unroll
        for (int ii = 0; ii < 4; ii++) ax[ii] = *(const float2*)&arow0[ii * 16 * SROW];
#pragma unroll
        for (int jj = 0; jj < 4; jj++) bx[jj] = *(const float2*)&brow0[jj * 16 * SROW];

#pragma unroll 2
        for (int hb = 0; hb < HH; hb += 4) {
            wy = *(const u64t*)&ws[hb + 2];
#pragma unroll
            for (int ii = 0; ii < 4; ii++)
                ay[ii] = *(const float2*)&arow0[ii * 16 * SROW + hb + 2];
#pragma unroll
            for (int jj = 0; jj < 4; jj++)
                by[jj] = *(const float2*)&brow0[jj * 16 * SROW + hb + 2];
#pragma unroll
            for (int jj = 0; jj < 4; jj++)
#pragma unroll
                for (int ii = 0; ii < 4; ii++)
                    max_fma2(acc[ii][jj], ax[ii].x, ax[ii].y, bx[jj].x, bx[jj].y, wx);
            wx = *(const u64t*)&ws[hb + 4];   // hb=60 -> reads padded ws[64..65]
#pragma unroll
            for (int ii = 0; ii < 4; ii++)
                ax[ii] = *(const float2*)&arow0[ii * 16 * SROW + hb + 4]; // in-row pad words
#pragma unroll
            for (int jj = 0; jj < 4; jj++)
                bx[jj] = *(const float2*)&brow0[jj * 16 * SROW + hb + 4];
#pragma unroll
            for (int jj = 0; jj < 4; jj++)
#pragma unroll
                for (int ii = 0; ii < 4; ii++)
                    max_fma2(acc[ii][jj], ay[ii].x, ay[ii].y, by[jj].x, by[jj].y, wy);
        }

#pragma unroll
        for (int ii = 0; ii < 4; ii++) {
            int gi = bi + ty + ii * 16;
#pragma unroll
            for (int jj = 0; jj < 4; jj++) {
                int gj = bj + tx + jj * 16;
                float2 v = *(float2*)&acc[ii][jj];
                float x = v.x + v.y + __ldg(&g_C[gj]) + bias;
                out[gi * NN + gj] = sigmoid_fast(x);
            }
        }

        if (tn >= NTILES) break;
        t = tn;
        p ^= 1;
    }
}

extern "C" void kernel_launch(void* const* d_in, const int* in_sizes, int n_in,
                              void* d_out, int out_size) {
    const float* Z  = (const float*)d_in[0];
    const float* W1 = (const float*)d_in[1];
    const float* b1 = (const float*)d_in[2];
    const float* W2 = (const float*)d_in[3];
    const float* b2 = (const float*)d_in[4];
    float* out = (float*)d_out;

    static const size_t SMEM_BYTES = (4 * ABUF + 68 + 4) * sizeof(float);
    cudaFuncSetAttribute(pair_kernel,
                         cudaFuncAttributeMaxDynamicSharedMemorySize,
                         (int)SMEM_BYTES);

    prep_kernel<<<NN / 4, 256>>>(Z, W1, b1, W2);
    pair_kernel<<<GRID, 256, SMEM_BYTES>>>(W2, b2, out);
}